// round 10
// baseline (speedup 1.0000x reference)
#include <cuda_runtime.h>
#include <math.h>

#define T_OBS   64
#define T_UNOBS 32
#define B       4096
#define D       4
#define H       256
#define G3      768    // 3*H
#define NSTEP   95     // 64 obs + 31 ar
#define SLABS   16     // row-slabs of 256 rows
#define UCS     8      // unit-chunks of 32 units
#define NCTAS   128    // SLABS * UCS, 1 CTA/SM, all co-resident

// ---------------- scratch (static device buffers; no allocation) ----------------
__device__ __align__(128) float g_H1[(size_t)T_OBS * B * H];  // stem out (tf32-rounded)
__device__ __align__(128) float g_Wc[G3 * H];                 // wi @ W2 folded (tf32-rounded)
__device__ __align__(128) float g_bc[G3];                     // bi + wi @ b2
__device__ __align__(128) float g_Wir[G3 * H];                // wi tf32-rounded
__device__ __align__(128) float g_Whr[G3 * H];                // wh tf32-rounded
__device__ __align__(128) float g_hf[2][B * H];               // hidden fp32 (ping-pong)
__device__ __align__(128) float g_ht[2][B * H];               // hidden tf32-rounded
__device__ unsigned g_gruCnt[SLABS];                          // per-slab step progress (monotone)

// ---------------- helpers ----------------
__device__ __forceinline__ float tf32r(float f) {
    unsigned u;
    asm("cvt.rna.tf32.f32 %0, %1;" : "=r"(u) : "f"(f));
    return __uint_as_float(u);
}

__device__ __forceinline__ void mma_tf32(float* c, const unsigned* a, const unsigned* b) {
    asm volatile(
        "mma.sync.aligned.m16n8k8.row.col.f32.tf32.tf32.f32 "
        "{%0,%1,%2,%3}, {%4,%5,%6,%7}, {%8,%9}, {%0,%1,%2,%3};"
        : "+f"(c[0]), "+f"(c[1]), "+f"(c[2]), "+f"(c[3])
        : "r"(a[0]), "r"(a[1]), "r"(a[2]), "r"(a[3]), "r"(b[0]), "r"(b[1]));
}

__device__ __forceinline__ void spin_ge(unsigned* p, unsigned tgt) {
    if (threadIdx.x == 0) {
        unsigned v;
        do {
            asm volatile("ld.acquire.gpu.u32 %0, [%1];" : "=r"(v) : "l"(p) : "memory");
            if (v < tgt) __nanosleep(32);
        } while (v < tgt);
    }
    __syncthreads();
}

__device__ __forceinline__ void signal(unsigned* p) {
    __syncthreads();
    if (threadIdx.x == 0) {
        __threadfence();
        atomicAdd(p, 1u);
    }
}

// ---------------- init ----------------
__global__ void zero_kernel() {
    int idx = blockIdx.x * blockDim.x + threadIdx.x;
    g_hf[0][idx] = 0.f;
    g_ht[0][idx] = 0.f;
    if (idx < SLABS) g_gruCnt[idx] = 0u;
}

__global__ void round_w_kernel(const float* __restrict__ wi, const float* __restrict__ wh) {
    int i = blockIdx.x * blockDim.x + threadIdx.x;
    g_Wir[i] = tf32r(wi[i]);
    g_Whr[i] = tf32r(wh[i]);
}

__global__ void wc_kernel(const float* __restrict__ wi, const float* __restrict__ w2,
                          const float* __restrict__ b2, const float* __restrict__ bi) {
    int j = blockIdx.x;   // 0..767
    int k = threadIdx.x;  // 0..255
    float acc = 0.f;
    for (int m = 0; m < H; m++)
        acc = fmaf(wi[j * H + m], w2[m * H + k], acc);
    g_Wc[j * H + k] = tf32r(acc);
    if (k == 0) {
        float a = bi[j];
        for (int m = 0; m < H; m++)
            a = fmaf(wi[j * H + m], b2[m], a);
        g_bc[j] = a;
    }
}

// ---------------- stem: h1 = tf32(leaky_relu([x, dt] @ W1^T + b1)), 16 rows/block ----------------
__global__ void stem_kernel(const float* __restrict__ x_obs, const float* __restrict__ t_obs,
                            const float* __restrict__ w1, const float* __restrict__ b1) {
    __shared__ float w1s[H * 5];
    __shared__ float b1s[H];
    __shared__ float xts[16][5];
    int tid = threadIdx.x;
    int r0 = blockIdx.x * 16;

    for (int i = tid; i < H * 5; i += 256) w1s[i] = w1[i];
    b1s[tid] = b1[tid];
    if (tid < 16) {
        int row = r0 + tid;
        float4 xv = *(const float4*)(x_obs + (size_t)row * 4);
        xts[tid][0] = xv.x; xts[tid][1] = xv.y; xts[tid][2] = xv.z; xts[tid][3] = xv.w;
        int t = row >> 12;
        xts[tid][4] = (t == 0) ? 0.f : (t_obs[row] - t_obs[row - B]);
    }
    __syncthreads();

    int cq = (tid & 63) * 4;
    int lr0 = tid >> 6;
    float wv[4][5], bb[4];
#pragma unroll
    for (int c = 0; c < 4; c++) {
        bb[c] = b1s[cq + c];
#pragma unroll
        for (int k = 0; k < 5; k++) wv[c][k] = w1s[(cq + c) * 5 + k];
    }
#pragma unroll
    for (int rr = 0; rr < 4; rr++) {
        int lr = lr0 + rr * 4;
        int row = r0 + lr;
        float4 o;
#pragma unroll
        for (int c = 0; c < 4; c++) {
            float acc = bb[c];
#pragma unroll
            for (int k = 0; k < 5; k++)
                acc = fmaf(wv[c][k], xts[lr][k], acc);
            float v = (acc > 0.f) ? acc : 0.01f * acc;
            (&o.x)[c] = tf32r(v);
        }
        *(float4*)(g_H1 + (size_t)row * H + cq) = o;
    }
}

// ---------------- per-step chunk engine (weight-stationary, GRU fused) ----------------
// ARP=false (obs): chunks of 16 rows; x-A = H1[t] (smem slot 0), h-A = ht (slot 4096). 16 chunks.
// ARP=true  (AR):  chunks of 32 rows; single A = ht (z==h). 8 chunks.
// Warps 0-3: x-path (weights SX), cols w*24.  Warps 4-7: h-path (SW), cols (w-4)*24.
template<bool ARP>
__device__ __forceinline__ void step_chunks(
    float* SX, float* SW, float* SA,
    const float* __restrict__ h1b, const float* __restrict__ htb,
    const float* __restrict__ hfo, float* __restrict__ hfn, float* __restrict__ htn,
    float* __restrict__ zso, int slab, int uc,
    float bxr, float bxz, float bxn, float bhr, float bhz, float bhn)
{
    constexpr int CH  = ARP ? 32 : 16;
    constexpr int NCH = ARP ? 8 : 16;
    constexpr int MSN = ARP ? 2 : 1;
    int tid = threadIdx.x;
    int warp = tid >> 5, lane = tid & 31;
    int q = lane >> 2, r = lane & 3;
    bool xw = (warp < 4);
    int wcol = (warp & 3) * 24;
    const float* Wb = xw ? SX : SW;
    int u = lane;                    // used via tid&31 below for GRU
    int gu = uc * 32 + (tid & 31);
    int base = slab * 256;
    float* SG = SA;                  // gate staging aliases A window

    float4 pf[8];

    // ---- chunk 0: load + store ----
    {
        int cb = base;
        if (ARP) {
            int rw = tid >> 3, f0 = tid & 7;
            const float* p = htb + (size_t)(cb + rw) * H;
#pragma unroll
            for (int s = 0; s < 8; s++) pf[s] = *(const float4*)(p + (f0 + 8 * s) * 4);
        } else {
            int rw = tid >> 4, f0 = tid & 15;
            const float* px = h1b + (size_t)(cb + rw) * H;
            const float* ph = htb + (size_t)(cb + rw) * H;
#pragma unroll
            for (int s = 0; s < 4; s++) {
                pf[s]     = *(const float4*)(px + (f0 + 16 * s) * 4);
                pf[4 + s] = *(const float4*)(ph + (f0 + 16 * s) * 4);
            }
        }
        if (ARP) {
            int rw = tid >> 3, f0 = tid & 7;
#pragma unroll
            for (int s = 0; s < 8; s++) {
                int f4 = f0 + 8 * s;
                *(float4*)(SA + rw * 256 + (((f4 ^ (rw & 7))) << 2)) = pf[s];
            }
        } else {
            int rw = tid >> 4, f0 = tid & 15;
#pragma unroll
            for (int s = 0; s < 4; s++) {
                int f4 = f0 + 16 * s;
                *(float4*)(SA + rw * 256 + ((f4 ^ (rw & 7)) << 2)) = pf[s];
                *(float4*)(SA + 4096 + rw * 256 + ((f4 ^ (rw & 7)) << 2)) = pf[4 + s];
            }
        }
    }
    __syncthreads();

    const float* Ab = ARP ? SA : (xw ? SA : SA + 4096);

    for (int ch = 0; ch < NCH; ch++) {
        // prefetch next chunk into registers
        if (ch + 1 < NCH) {
            int cb = base + (ch + 1) * CH;
            if (ARP) {
                int rw = tid >> 3, f0 = tid & 7;
                const float* p = htb + (size_t)(cb + rw) * H;
#pragma unroll
                for (int s = 0; s < 8; s++) pf[s] = *(const float4*)(p + (f0 + 8 * s) * 4);
            } else {
                int rw = tid >> 4, f0 = tid & 15;
                const float* px = h1b + (size_t)(cb + rw) * H;
                const float* ph = htb + (size_t)(cb + rw) * H;
#pragma unroll
                for (int s = 0; s < 4; s++) {
                    pf[s]     = *(const float4*)(px + (f0 + 16 * s) * 4);
                    pf[4 + s] = *(const float4*)(ph + (f0 + 16 * s) * 4);
                }
            }
        }

        // ---- MMA over K=256 ----
        float acc[MSN][3][4];
#pragma unroll
        for (int ms = 0; ms < MSN; ms++)
#pragma unroll
            for (int ns = 0; ns < 3; ns++)
#pragma unroll
                for (int j = 0; j < 4; j++) acc[ms][ns][j] = 0.f;

        int sw = q << 2;
#pragma unroll 1
        for (int kc = 0; kc < 32; kc++) {
            int k0 = kc * 8 + r;
            unsigned bfr[3][2];
#pragma unroll
            for (int ns = 0; ns < 3; ns++) {
                int cn = wcol + ns * 8 + q;
                bfr[ns][0] = __float_as_uint(Wb[cn * 256 + (k0 ^ sw)]);
                bfr[ns][1] = __float_as_uint(Wb[cn * 256 + ((k0 + 4) ^ sw)]);
            }
#pragma unroll
            for (int ms = 0; ms < MSN; ms++) {
                int rm = ms * 16 + q;
                unsigned af[4];
                af[0] = __float_as_uint(Ab[rm * 256 + (k0 ^ sw)]);
                af[1] = __float_as_uint(Ab[(rm + 8) * 256 + (k0 ^ sw)]);
                af[2] = __float_as_uint(Ab[rm * 256 + ((k0 + 4) ^ sw)]);
                af[3] = __float_as_uint(Ab[(rm + 8) * 256 + ((k0 + 4) ^ sw)]);
#pragma unroll
                for (int ns = 0; ns < 3; ns++)
                    mma_tf32(acc[ms][ns], af, bfr[ns]);
            }
        }
        __syncthreads();   // done reading SA

        // ---- stage gates into SG (alias of SA): col = path*96 + gate*32 + unit ----
#pragma unroll
        for (int ms = 0; ms < MSN; ms++)
#pragma unroll
            for (int ns = 0; ns < 3; ns++) {
                int c0 = (xw ? 0 : 96) + wcol + ns * 8 + 2 * r;
                int r0 = ms * 16 + q;
                *(float2*)(SG + r0 * 200 + c0) = make_float2(acc[ms][ns][0], acc[ms][ns][1]);
                *(float2*)(SG + (r0 + 8) * 200 + c0) = make_float2(acc[ms][ns][2], acc[ms][ns][3]);
            }
        __syncthreads();

        // ---- fused GRU for this chunk ----
        {
            int cb = base + ch * CH;
            int uu = tid & 31;
#pragma unroll
            for (int it = 0; it < CH / 8; it++) {
                int rr = (tid >> 5) + it * 8;
                float gxr = SG[rr * 200 + uu] + bxr;
                float gxz = SG[rr * 200 + 32 + uu] + bxz;
                float gxn = SG[rr * 200 + 64 + uu] + bxn;
                float ghr = SG[rr * 200 + 96 + uu] + bhr;
                float ghz = SG[rr * 200 + 128 + uu] + bhz;
                float ghn = SG[rr * 200 + 160 + uu] + bhn;
                float rg = 1.f / (1.f + expf(-(gxr + ghr)));
                float ug = 1.f / (1.f + expf(-(gxz + ghz)));
                float nn = tanhf(gxn + rg * ghn);
                size_t idx = (size_t)(cb + rr) * H + gu;
                float hp = hfo[idx];
                float hv = (1.f - ug) * nn + ug * hp;
                hfn[idx] = hv;
                htn[idx] = tf32r(hv);
                if (zso) zso[idx] = hv;
            }
        }
        __syncthreads();   // done reading SG

        // ---- publish next chunk A ----
        if (ch + 1 < NCH) {
            if (ARP) {
                int rw = tid >> 3, f0 = tid & 7;
#pragma unroll
                for (int s = 0; s < 8; s++) {
                    int f4 = f0 + 8 * s;
                    *(float4*)(SA + rw * 256 + ((f4 ^ (rw & 7)) << 2)) = pf[s];
                }
            } else {
                int rw = tid >> 4, f0 = tid & 15;
#pragma unroll
                for (int s = 0; s < 4; s++) {
                    int f4 = f0 + 16 * s;
                    *(float4*)(SA + rw * 256 + ((f4 ^ (rw & 7)) << 2)) = pf[s];
                    *(float4*)(SA + 4096 + rw * 256 + ((f4 ^ (rw & 7)) << 2)) = pf[4 + s];
                }
            }
            __syncthreads();
        }
    }
}

// ---------------- persistent weight-stationary recurrence ----------------
__global__ __launch_bounds__(256, 1) void rnn_ws(
    const float* __restrict__ bi, const float* __restrict__ bh,
    float* __restrict__ zs_base)
{
    extern __shared__ float sm[];
    float* SX = sm;               // 96 x 256 (Wc rows, then wi rows)
    float* SW = sm + 96 * 256;    // 96 x 256 (wh rows)
    float* SA = sm + 2 * 96 * 256;// 32 x 256 A window (aliases gate staging)

    int tid = threadIdx.x;
    int uc = blockIdx.x & 7;
    int slab = blockIdx.x >> 3;
    int gu = uc * 32 + (tid & 31);

    float bhr = bh[gu], bhz = bh[256 + gu], bhn = bh[512 + gu];
    float bxr = 0.f, bxz = 0.f, bxn = 0.f;

    for (int step = 0; step < NSTEP; step++) {
        bool ar = (step >= T_OBS);
        int par = step & 1;

        if (step == 0) {
            for (int i = tid; i < 96 * 64; i += 256) {
                int row = i >> 6, f4 = i & 63;
                size_t gr = (size_t)((row >> 5) * 256 + uc * 32 + (row & 31)) * H + f4 * 4;
                *(float4*)(SX + row * 256 + ((f4 ^ (row & 7)) << 2)) = *(const float4*)(g_Wc + gr);
                *(float4*)(SW + row * 256 + ((f4 ^ (row & 7)) << 2)) = *(const float4*)(g_Whr + gr);
            }
            bxr = g_bc[gu]; bxz = g_bc[256 + gu]; bxn = g_bc[512 + gu];
            __syncthreads();
        } else if (step == T_OBS) {
            // safe: previous step ended with signal()'s __syncthreads
            for (int i = tid; i < 96 * 64; i += 256) {
                int row = i >> 6, f4 = i & 63;
                size_t gr = (size_t)((row >> 5) * 256 + uc * 32 + (row & 31)) * H + f4 * 4;
                *(float4*)(SX + row * 256 + ((f4 ^ (row & 7)) << 2)) = *(const float4*)(g_Wir + gr);
            }
            bxr = bi[gu]; bxz = bi[256 + gu]; bxn = bi[512 + gu];
        }

        if (step) spin_ge(&g_gruCnt[slab], 8u * step);   // includes __syncthreads (publishes SX too)

        const float* htb = g_ht[par];
        const float* hfo = g_hf[par];
        float* hfn = g_hf[par ^ 1];
        float* htn = g_ht[par ^ 1];
        float* zso = nullptr;
        if (step == T_OBS - 1)      zso = zs_base;
        else if (ar)                zso = zs_base + (size_t)(step - (T_OBS - 1)) * B * H;

        if (!ar) {
            const float* h1b = g_H1 + (size_t)step * B * H;
            step_chunks<false>(SX, SW, SA, h1b, htb, hfo, hfn, htn, zso, slab, uc,
                               bxr, bxz, bxn, bhr, bhz, bhn);
        } else {
            step_chunks<true>(SX, SW, SA, nullptr, htb, hfo, hfn, htn, zso, slab, uc,
                              bxr, bxz, bxn, bhr, bhz, bhn);
        }

        signal(&g_gruCnt[slab]);
    }
}

// ---------------- head: x_hats = zs @ head_w^T + head_b ----------------
__global__ void head_kernel(const float* __restrict__ zs, const float* __restrict__ head_w,
                            const float* __restrict__ head_b, float* __restrict__ xh) {
    int row = blockIdx.x * 8 + (threadIdx.x >> 5);
    int lane = threadIdx.x & 31;
    const float* z = zs + (size_t)row * H;
    float acc[4] = {0.f, 0.f, 0.f, 0.f};
    for (int c = lane; c < H; c += 32) {
        float zv = z[c];
#pragma unroll
        for (int d = 0; d < 4; d++)
            acc[d] = fmaf(zv, head_w[d * H + c], acc[d]);
    }
#pragma unroll
    for (int d = 0; d < 4; d++)
        for (int off = 16; off; off >>= 1)
            acc[d] += __shfl_xor_sync(0xFFFFFFFFu, acc[d], off);
    if (lane < 4)
        xh[(size_t)row * 4 + lane] = acc[lane] + head_b[lane];
}

// ---------------- launch ----------------
extern "C" void kernel_launch(void* const* d_in, const int* in_sizes, int n_in,
                              void* d_out, int out_size) {
    const float* x_obs   = (const float*)d_in[0];
    const float* t_obs   = (const float*)d_in[1];
    const float* stem_w1 = (const float*)d_in[3];
    const float* stem_b1 = (const float*)d_in[4];
    const float* stem_w2 = (const float*)d_in[5];
    const float* stem_b2 = (const float*)d_in[6];
    const float* gru_wi  = (const float*)d_in[7];
    const float* gru_wh  = (const float*)d_in[8];
    const float* gru_bi  = (const float*)d_in[9];
    const float* gru_bh  = (const float*)d_in[10];
    const float* head_w  = (const float*)d_in[11];
    const float* head_b  = (const float*)d_in[12];

    float* out    = (float*)d_out;
    float* x_hats = out;                                 // [32,4096,4]
    float* zs     = out + (size_t)T_UNOBS * B * D;       // [32,4096,256]

    const int SMEM = (2 * 96 * 256 + 32 * 256) * 4;      // 229376 bytes
    cudaFuncSetAttribute(rnn_ws, cudaFuncAttributeMaxDynamicSharedMemorySize, SMEM);

    zero_kernel<<<(B * H) / 256, 256>>>();
    round_w_kernel<<<(G3 * H) / 256, 256>>>(gru_wi, gru_wh);
    wc_kernel<<<G3, H>>>(gru_wi, stem_w2, stem_b2, gru_bi);
    stem_kernel<<<T_OBS * B / 16, 256>>>(x_obs, t_obs, stem_w1, stem_b1);

    rnn_ws<<<NCTAS, 256, SMEM>>>(gru_bi, gru_bh, zs);

    head_kernel<<<(T_UNOBS * B) / 8, 256>>>(zs, head_w, head_b, x_hats);
}

// round 12
// speedup vs baseline: 1.9097x; 1.9097x over previous
#include <cuda_runtime.h>
#include <cuda_fp16.h>
#include <math.h>

#define T_OBS   64
#define T_UNOBS 32
#define B       4096
#define D       4
#define H       256
#define G3      768    // 3*H
#define NSTEP   95     // 64 obs + 31 ar
#define NCTA    296    // 2 CTAs/SM on 148 SMs -> co-resident
#define SLABS   32     // m-slabs of 128 rows
#define GRUCH   256    // GRU chunks (16 rows), chunk r in slab r>>3
#define STAGES  4
#define BK      32     // k-chunk in halves
#define SROW    40     // smem row stride in halves (32 + 8 pad -> 80B rows)

// ---------------- scratch (static device buffers; no allocation) ----------------
__device__ __align__(128) __half g_H1h[(size_t)T_OBS * B * H]; // stem out (fp16)
__device__ __align__(128) __half g_Wch[G3 * H];                // wi @ W2 folded (fp16)
__device__ __align__(128) float  g_bc[G3];                     // bi + wi @ b2 (fp32)
__device__ __align__(128) __half g_Wih[G3 * H];                // wi (fp16)
__device__ __align__(128) __half g_Whh[G3 * H];                // wh (fp16)
__device__ __align__(128) float  g_hf[2][B * H];               // hidden fp32 (ping-pong)
__device__ __align__(128) __half g_hth[2][B * H];              // hidden fp16 (ping-pong)
__device__ __align__(128) float  g_G[2][(size_t)B * 2 * G3];   // gates [gx | gh], parity-buffered
__device__ unsigned g_tileCnt[SLABS];   // 12 signals/slab/step (monotone)
__device__ unsigned g_gruCnt[SLABS];    // 8 signals/slab/step (monotone)

// ---------------- helpers ----------------
__device__ __forceinline__ void mma_f16(float* c, const unsigned* a, const unsigned* b) {
    asm volatile(
        "mma.sync.aligned.m16n8k16.row.col.f32.f16.f16.f32 "
        "{%0,%1,%2,%3}, {%4,%5,%6,%7}, {%8,%9}, {%0,%1,%2,%3};"
        : "+f"(c[0]), "+f"(c[1]), "+f"(c[2]), "+f"(c[3])
        : "r"(a[0]), "r"(a[1]), "r"(a[2]), "r"(a[3]), "r"(b[0]), "r"(b[1]));
}

__device__ __forceinline__ void cp16(void* smem, const void* gmem) {
    unsigned s = (unsigned)__cvta_generic_to_shared(smem);
    asm volatile("cp.async.cg.shared.global [%0], [%1], 16;" :: "r"(s), "l"(gmem));
}

__device__ __forceinline__ void spin_ge(unsigned* p, unsigned tgt) {
    if (threadIdx.x == 0) {
        unsigned v;
        do {
            asm volatile("ld.acquire.gpu.u32 %0, [%1];" : "=r"(v) : "l"(p) : "memory");
            if (v < tgt) __nanosleep(32);
        } while (v < tgt);
    }
    __syncthreads();
}

__device__ __forceinline__ void signal(unsigned* p) {
    __syncthreads();
    if (threadIdx.x == 0) {
        __threadfence();
        atomicAdd(p, 1u);
    }
}

// ---------------- init ----------------
__global__ void zero_kernel() {
    int idx = blockIdx.x * blockDim.x + threadIdx.x;
    g_hf[0][idx] = 0.f;
    g_hth[0][idx] = __float2half(0.f);
    if (idx < SLABS) { g_tileCnt[idx] = 0u; g_gruCnt[idx] = 0u; }
}

__global__ void round_w_kernel(const float* __restrict__ wi, const float* __restrict__ wh) {
    int i = blockIdx.x * blockDim.x + threadIdx.x;
    g_Wih[i] = __float2half_rn(wi[i]);
    g_Whh[i] = __float2half_rn(wh[i]);
}

__global__ void wc_kernel(const float* __restrict__ wi, const float* __restrict__ w2,
                          const float* __restrict__ b2, const float* __restrict__ bi) {
    int j = blockIdx.x;   // 0..767
    int k = threadIdx.x;  // 0..255
    float acc = 0.f;
    for (int m = 0; m < H; m++)
        acc = fmaf(wi[j * H + m], w2[m * H + k], acc);
    g_Wch[j * H + k] = __float2half_rn(acc);
    if (k == 0) {
        float a = bi[j];
        for (int m = 0; m < H; m++)
            a = fmaf(wi[j * H + m], b2[m], a);
        g_bc[j] = a;
    }
}

// ---------------- stem: h1 = fp16(leaky_relu([x, dt] @ W1^T + b1)), 16 rows/block ----------------
__global__ void stem_kernel(const float* __restrict__ x_obs, const float* __restrict__ t_obs,
                            const float* __restrict__ w1, const float* __restrict__ b1) {
    __shared__ float w1s[H * 5];
    __shared__ float b1s[H];
    __shared__ float xts[16][5];
    int tid = threadIdx.x;
    int r0 = blockIdx.x * 16;

    for (int i = tid; i < H * 5; i += 256) w1s[i] = w1[i];
    b1s[tid] = b1[tid];
    if (tid < 16) {
        int row = r0 + tid;
        float4 xv = *(const float4*)(x_obs + (size_t)row * 4);
        xts[tid][0] = xv.x; xts[tid][1] = xv.y; xts[tid][2] = xv.z; xts[tid][3] = xv.w;
        int t = row >> 12;
        xts[tid][4] = (t == 0) ? 0.f : (t_obs[row] - t_obs[row - B]);
    }
    __syncthreads();

    int cq = (tid & 63) * 4;
    int lr0 = tid >> 6;
    float wv[4][5], bb[4];
#pragma unroll
    for (int c = 0; c < 4; c++) {
        bb[c] = b1s[cq + c];
#pragma unroll
        for (int k = 0; k < 5; k++) wv[c][k] = w1s[(cq + c) * 5 + k];
    }
#pragma unroll
    for (int rr = 0; rr < 4; rr++) {
        int lr = lr0 + rr * 4;
        int row = r0 + lr;
        float o[4];
#pragma unroll
        for (int c = 0; c < 4; c++) {
            float acc = bb[c];
#pragma unroll
            for (int k = 0; k < 5; k++)
                acc = fmaf(wv[c][k], xts[lr][k], acc);
            o[c] = (acc > 0.f) ? acc : 0.01f * acc;
        }
        __half2* dst = (__half2*)(g_H1h + (size_t)row * H + cq);
        dst[0] = __floats2half2_rn(o[0], o[1]);
        dst[1] = __floats2half2_rn(o[2], o[3]);
    }
}

// ---------------- persistent recurrence: dataflow sync + cp.async fp16 m16n8k16 GEMM ----------------
__global__ __launch_bounds__(256, 2) void rnn_persistent(
    const float* __restrict__ bi, const float* __restrict__ bh,
    float* __restrict__ zs_base) {
    extern __shared__ __half smh[];
    __half (*As)[128 * SROW] = (__half (*)[128 * SROW])smh;
    __half (*Bs)[128 * SROW] = (__half (*)[128 * SROW])(smh + STAGES * 128 * SROW);

    int tid = threadIdx.x, warp = tid >> 5, lane = tid & 31;
    int q = lane >> 2, r = lane & 3;
    int wm = warp & 3, wn = warp >> 2;
    int rank = blockIdx.x;

    for (int step = 0; step < NSTEP; step++) {
        int par = step & 1;
        bool ar = (step >= T_OBS);
        const __half* hA = g_hth[par];
        float* Gw = g_G[par];

        // ---- GEMM tiles (dataflow gated per slab) ----
        for (int tile = rank; tile < 384; tile += NCTA) {
            int tn = tile >> 5;        // 0..11
            int tm = tile & 31;        // slab
            bool needsH = ar || (tn >= 6);
            unsigned tgt = needsH ? 8u * step : (step ? 8u * (step - 1) : 0u);
            if (tgt) spin_ge(&g_gruCnt[tm], tgt);

            const __half* A;
            const __half* W;
            if (tn < 6) {
                A = ar ? hA : (g_H1h + (size_t)step * B * H);
                W = ar ? g_Wih : g_Wch;
            } else {
                A = hA;
                W = g_Whh;
            }
            int wrow = (tn < 6 ? tn : tn - 6) * 128;
            int gcol = tn * 128;
            int mbase = tm * 128;
            const __half* Abase = A + (size_t)mbase * H;
            const __half* Wbase = W + (size_t)wrow * H;

            // per-thread cp.async coords: 2 ops per operand per stage
            int rowA0 = tid >> 1;                 // covers 0..127 with l: row = (tid+l*256)>>1
            float acc[2][8][4] = {};

            __syncthreads();   // smem reuse guard across tiles

            // prologue: stages 0..2
#pragma unroll
            for (int s = 0; s < STAGES - 1; s++) {
                int k0 = s * BK;
#pragma unroll
                for (int l = 0; l < 2; l++) {
                    int c = tid + l * 256;
                    int row = c >> 2, seg = c & 3;        // seg = 8-half chunk
                    cp16(&As[s][row * SROW + seg * 8], Abase + (size_t)row * H + k0 + seg * 8);
                    cp16(&Bs[s][row * SROW + seg * 8], Wbase + (size_t)row * H + k0 + seg * 8);
                }
                asm volatile("cp.async.commit_group;");
            }

#pragma unroll 1
            for (int kc = 0; kc < 8; kc++) {       // 8 chunks of 32
                asm volatile("cp.async.wait_group %0;" :: "n"(STAGES - 2));
                __syncthreads();
                int buf = kc & (STAGES - 1);

                if (kc + STAGES - 1 < 8) {
                    int s = (kc + STAGES - 1) & (STAGES - 1);
                    int k0 = (kc + STAGES - 1) * BK;
#pragma unroll
                    for (int l = 0; l < 2; l++) {
                        int c = tid + l * 256;
                        int row = c >> 2, seg = c & 3;
                        cp16(&As[s][row * SROW + seg * 8], Abase + (size_t)row * H + k0 + seg * 8);
                        cp16(&Bs[s][row * SROW + seg * 8], Wbase + (size_t)row * H + k0 + seg * 8);
                    }
                }
                asm volatile("cp.async.commit_group;");

                const __half* Ab = As[buf];
                const __half* Bb = Bs[buf];
#pragma unroll
                for (int ks = 0; ks < 2; ks++) {   // 2 k16 steps per chunk
                    int kk = ks * 16;
                    unsigned af[2][4], bf[8][2];
#pragma unroll
                    for (int mi = 0; mi < 2; mi++) {
                        int rm = wm * 32 + mi * 16 + q;
                        af[mi][0] = *(const unsigned*)&Ab[rm * SROW + kk + 2 * r];
                        af[mi][1] = *(const unsigned*)&Ab[(rm + 8) * SROW + kk + 2 * r];
                        af[mi][2] = *(const unsigned*)&Ab[rm * SROW + kk + 2 * r + 8];
                        af[mi][3] = *(const unsigned*)&Ab[(rm + 8) * SROW + kk + 2 * r + 8];
                    }
#pragma unroll
                    for (int ni = 0; ni < 8; ni++) {
                        int cn = wn * 64 + ni * 8 + q;
                        bf[ni][0] = *(const unsigned*)&Bb[cn * SROW + kk + 2 * r];
                        bf[ni][1] = *(const unsigned*)&Bb[cn * SROW + kk + 2 * r + 8];
                    }
#pragma unroll
                    for (int mi = 0; mi < 2; mi++)
#pragma unroll
                        for (int ni = 0; ni < 8; ni++)
                            mma_f16(acc[mi][ni], af[mi], bf[ni]);
                }
            }

#pragma unroll
            for (int mi = 0; mi < 2; mi++) {
                int row = mbase + wm * 32 + mi * 16 + q;
#pragma unroll
                for (int ni = 0; ni < 8; ni++) {
                    int cl = wn * 64 + ni * 8 + 2 * r;
                    *(float2*)&Gw[(size_t)row * (2 * G3) + gcol + cl] =
                        make_float2(acc[mi][ni][0], acc[mi][ni][1]);
                    *(float2*)&Gw[(size_t)(row + 8) * (2 * G3) + gcol + cl] =
                        make_float2(acc[mi][ni][2], acc[mi][ni][3]);
                }
            }
            signal(&g_tileCnt[tm]);
        }

        // ---- GRU chunk (16 rows), gated on this slab's 12 tiles ----
        if (rank < GRUCH) {
            int slab = rank >> 3;
            spin_ge(&g_tileCnt[slab], 12u * (step + 1));

            const float* bxi = ar ? bi : g_bc;
            float* hfn = g_hf[par ^ 1];
            __half* htn = g_hth[par ^ 1];
            const float* hfo = g_hf[par];
            float* zs_out = nullptr;
            if (step == T_OBS - 1)      zs_out = zs_base;
            else if (ar)                zs_out = zs_base + (size_t)(step - (T_OBS - 1)) * B * H;

            int row0 = rank * 16;
            for (int i = tid; i < 16 * 64; i += 256) {
                int b = row0 + (i >> 6);
                int m4 = (i & 63) * 4;
                const float* g = Gw + (size_t)b * (2 * G3);
                float4 rx = *(const float4*)(g + m4);
                float4 zx = *(const float4*)(g + H + m4);
                float4 nx = *(const float4*)(g + 2 * H + m4);
                float4 rh = *(const float4*)(g + G3 + m4);
                float4 zh = *(const float4*)(g + G3 + H + m4);
                float4 nh = *(const float4*)(g + G3 + 2 * H + m4);
                float4 br = *(const float4*)(bxi + m4);
                float4 bz = *(const float4*)(bxi + H + m4);
                float4 bn = *(const float4*)(bxi + 2 * H + m4);
                float4 cr = *(const float4*)(bh + m4);
                float4 cz = *(const float4*)(bh + H + m4);
                float4 cn = *(const float4*)(bh + 2 * H + m4);
                float4 hp = *(const float4*)(hfo + (size_t)b * H + m4);
                float4 hn4;
                __half2 hh[2];
#pragma unroll
                for (int c = 0; c < 4; c++) {
                    float gxr = (&rx.x)[c] + (&br.x)[c];
                    float gxz = (&zx.x)[c] + (&bz.x)[c];
                    float gxn = (&nx.x)[c] + (&bn.x)[c];
                    float ghr = (&rh.x)[c] + (&cr.x)[c];
                    float ghz = (&zh.x)[c] + (&cz.x)[c];
                    float ghn = (&nh.x)[c] + (&cn.x)[c];
                    float rr = 1.f / (1.f + expf(-(gxr + ghr)));
                    float ug = 1.f / (1.f + expf(-(gxz + ghz)));
                    float nn = tanhf(gxn + rr * ghn);
                    (&hn4.x)[c] = (1.f - ug) * nn + ug * (&hp.x)[c];
                }
                hh[0] = __floats2half2_rn(hn4.x, hn4.y);
                hh[1] = __floats2half2_rn(hn4.z, hn4.w);
                *(float4*)(hfn + (size_t)b * H + m4) = hn4;
                *(__half2*)(htn + (size_t)b * H + m4)     = hh[0];
                *(__half2*)(htn + (size_t)b * H + m4 + 2) = hh[1];
                if (zs_out) *(float4*)(zs_out + (size_t)b * H + m4) = hn4;
            }
            signal(&g_gruCnt[slab]);
        }
    }
}

// ---------------- head: x_hats = zs @ head_w^T + head_b ----------------
__global__ void head_kernel(const float* __restrict__ zs, const float* __restrict__ head_w,
                            const float* __restrict__ head_b, float* __restrict__ xh) {
    int row = blockIdx.x * 8 + (threadIdx.x >> 5);
    int lane = threadIdx.x & 31;
    const float* z = zs + (size_t)row * H;
    float acc[4] = {0.f, 0.f, 0.f, 0.f};
    for (int c = lane; c < H; c += 32) {
        float zv = z[c];
#pragma unroll
        for (int d = 0; d < 4; d++)
            acc[d] = fmaf(zv, head_w[d * H + c], acc[d]);
    }
#pragma unroll
    for (int d = 0; d < 4; d++)
        for (int off = 16; off; off >>= 1)
            acc[d] += __shfl_xor_sync(0xFFFFFFFFu, acc[d], off);
    if (lane < 4)
        xh[(size_t)row * 4 + lane] = acc[lane] + head_b[lane];
}

// ---------------- launch ----------------
extern "C" void kernel_launch(void* const* d_in, const int* in_sizes, int n_in,
                              void* d_out, int out_size) {
    const float* x_obs   = (const float*)d_in[0];
    const float* t_obs   = (const float*)d_in[1];
    const float* stem_w1 = (const float*)d_in[3];
    const float* stem_b1 = (const float*)d_in[4];
    const float* stem_w2 = (const float*)d_in[5];
    const float* stem_b2 = (const float*)d_in[6];
    const float* gru_wi  = (const float*)d_in[7];
    const float* gru_wh  = (const float*)d_in[8];
    const float* gru_bi  = (const float*)d_in[9];
    const float* gru_bh  = (const float*)d_in[10];
    const float* head_w  = (const float*)d_in[11];
    const float* head_b  = (const float*)d_in[12];

    float* out    = (float*)d_out;
    float* x_hats = out;                                 // [32,4096,4]
    float* zs     = out + (size_t)T_UNOBS * B * D;       // [32,4096,256]

    const int SMEM = STAGES * 128 * SROW * 2 * 2;        // 81920 bytes
    cudaFuncSetAttribute(rnn_persistent,
                         cudaFuncAttributeMaxDynamicSharedMemorySize, SMEM);

    zero_kernel<<<(B * H) / 256, 256>>>();
    round_w_kernel<<<(G3 * H) / 256, 256>>>(gru_wi, gru_wh);
    wc_kernel<<<G3, H>>>(gru_wi, stem_w2, stem_b2, gru_bi);
    stem_kernel<<<T_OBS * B / 16, 256>>>(x_obs, t_obs, stem_w1, stem_b1);

    rnn_persistent<<<NCTA, 256, SMEM>>>(gru_bi, gru_bh, zs);

    head_kernel<<<(T_UNOBS * B) / 8, 256>>>(zs, head_w, head_b, x_hats);
}

// round 13
// speedup vs baseline: 1.9319x; 1.0116x over previous
#include <cuda_runtime.h>
#include <cuda_fp16.h>
#include <math.h>

#define T_OBS   64
#define T_UNOBS 32
#define B       4096
#define D       4
#define H       256
#define G3      768    // 3*H
#define NSTEP   95     // 64 obs + 31 ar
#define NCTA    296    // 2 CTAs/SM on 148 SMs -> co-resident
#define SLABS   32     // m-slabs of 128 rows
#define GRUCH   256    // GRU chunks (16 rows), chunk r in slab r>>3
#define STAGES  4
#define BK      32     // k-chunk in halves
#define SROW    40     // smem row stride in halves (32 + 8 pad -> 80B rows)

// ---------------- scratch (static device buffers; no allocation) ----------------
__device__ __align__(128) __half g_H1h[(size_t)T_OBS * B * H]; // stem out (fp16)
__device__ __align__(128) __half g_Wch[G3 * H];                // wi @ W2 folded (fp16)
__device__ __align__(128) float  g_bc[G3];                     // bi + wi @ b2 (fp32)
__device__ __align__(128) __half g_Wih[G3 * H];                // wi (fp16)
__device__ __align__(128) __half g_Whh[G3 * H];                // wh (fp16)
__device__ __align__(128) float  g_hf[2][B * H];               // hidden fp32 (ping-pong)
__device__ __align__(128) __half g_hth[2][B * H];              // hidden fp16 (ping-pong)
__device__ __align__(128) float  g_G[2][(size_t)B * 2 * G3];   // gates [gx | gh], parity-buffered
__device__ unsigned g_tileCnt[SLABS];   // 12 signals/slab/step (monotone)
__device__ unsigned g_gruCnt[SLABS];    // 8 signals/slab/step (monotone)

// ---------------- helpers ----------------
__device__ __forceinline__ void mma_f16(float* c, const unsigned* a, const unsigned* b) {
    asm volatile(
        "mma.sync.aligned.m16n8k16.row.col.f32.f16.f16.f32 "
        "{%0,%1,%2,%3}, {%4,%5,%6,%7}, {%8,%9}, {%0,%1,%2,%3};"
        : "+f"(c[0]), "+f"(c[1]), "+f"(c[2]), "+f"(c[3])
        : "r"(a[0]), "r"(a[1]), "r"(a[2]), "r"(a[3]), "r"(b[0]), "r"(b[1]));
}

__device__ __forceinline__ void cp16(void* smem, const void* gmem) {
    unsigned s = (unsigned)__cvta_generic_to_shared(smem);
    asm volatile("cp.async.cg.shared.global [%0], [%1], 16;" :: "r"(s), "l"(gmem));
}

__device__ __forceinline__ void spin_ge(unsigned* p, unsigned tgt) {
    if (threadIdx.x == 0) {
        unsigned v;
        do {
            asm volatile("ld.acquire.gpu.u32 %0, [%1];" : "=r"(v) : "l"(p) : "memory");
            if (v < tgt) __nanosleep(32);
        } while (v < tgt);
    }
    __syncthreads();
}

__device__ __forceinline__ void signal(unsigned* p) {
    __syncthreads();
    if (threadIdx.x == 0) {
        __threadfence();
        atomicAdd(p, 1u);
    }
}

// ---------------- init ----------------
__global__ void zero_kernel() {
    int idx = blockIdx.x * blockDim.x + threadIdx.x;
    g_hf[0][idx] = 0.f;
    g_hth[0][idx] = __float2half(0.f);
    if (idx < SLABS) { g_tileCnt[idx] = 0u; g_gruCnt[idx] = 0u; }
}

__global__ void round_w_kernel(const float* __restrict__ wi, const float* __restrict__ wh) {
    int i = blockIdx.x * blockDim.x + threadIdx.x;
    g_Wih[i] = __float2half_rn(wi[i]);
    g_Whh[i] = __float2half_rn(wh[i]);
}

__global__ void wc_kernel(const float* __restrict__ wi, const float* __restrict__ w2,
                          const float* __restrict__ b2, const float* __restrict__ bi) {
    int j = blockIdx.x;   // 0..767
    int k = threadIdx.x;  // 0..255
    float acc = 0.f;
    for (int m = 0; m < H; m++)
        acc = fmaf(wi[j * H + m], w2[m * H + k], acc);
    g_Wch[j * H + k] = __float2half_rn(acc);
    if (k == 0) {
        float a = bi[j];
        for (int m = 0; m < H; m++)
            a = fmaf(wi[j * H + m], b2[m], a);
        g_bc[j] = a;
    }
}

// ---------------- stem: h1 = fp16(leaky_relu([x, dt] @ W1^T + b1)), 16 rows/block ----------------
__global__ void stem_kernel(const float* __restrict__ x_obs, const float* __restrict__ t_obs,
                            const float* __restrict__ w1, const float* __restrict__ b1) {
    __shared__ float w1s[H * 5];
    __shared__ float b1s[H];
    __shared__ float xts[16][5];
    int tid = threadIdx.x;
    int r0 = blockIdx.x * 16;

    for (int i = tid; i < H * 5; i += 256) w1s[i] = w1[i];
    b1s[tid] = b1[tid];
    if (tid < 16) {
        int row = r0 + tid;
        float4 xv = *(const float4*)(x_obs + (size_t)row * 4);
        xts[tid][0] = xv.x; xts[tid][1] = xv.y; xts[tid][2] = xv.z; xts[tid][3] = xv.w;
        int t = row >> 12;
        xts[tid][4] = (t == 0) ? 0.f : (t_obs[row] - t_obs[row - B]);
    }
    __syncthreads();

    int cq = (tid & 63) * 4;
    int lr0 = tid >> 6;
    float wv[4][5], bb[4];
#pragma unroll
    for (int c = 0; c < 4; c++) {
        bb[c] = b1s[cq + c];
#pragma unroll
        for (int k = 0; k < 5; k++) wv[c][k] = w1s[(cq + c) * 5 + k];
    }
#pragma unroll
    for (int rr = 0; rr < 4; rr++) {
        int lr = lr0 + rr * 4;
        int row = r0 + lr;
        float o[4];
#pragma unroll
        for (int c = 0; c < 4; c++) {
            float acc = bb[c];
#pragma unroll
            for (int k = 0; k < 5; k++)
                acc = fmaf(wv[c][k], xts[lr][k], acc);
            o[c] = (acc > 0.f) ? acc : 0.01f * acc;
        }
        __half2* dst = (__half2*)(g_H1h + (size_t)row * H + cq);
        dst[0] = __floats2half2_rn(o[0], o[1]);
        dst[1] = __floats2half2_rn(o[2], o[3]);
    }
}

// ---------------- persistent recurrence: role-partitioned tiles + fp16 MMA ----------------
// Tile ids: 0..191 = x-path (tn 0..5), 192..383 = h-path (tn 6..11).
// Ranks 0..103 own x tiles {rank, rank+104<192}; ranks 104..295 own h tile {rank+88}.
// x tiles run one step ahead of the recurrence; h tiles are the critical path.
__global__ __launch_bounds__(256, 2) void rnn_persistent(
    const float* __restrict__ bi, const float* __restrict__ bh,
    float* __restrict__ zs_base) {
    extern __shared__ __half smh[];
    __half (*As)[128 * SROW] = (__half (*)[128 * SROW])smh;
    __half (*Bs)[128 * SROW] = (__half (*)[128 * SROW])(smh + STAGES * 128 * SROW);

    int tid = threadIdx.x, warp = tid >> 5, lane = tid & 31;
    int q = lane >> 2, r = lane & 3;
    int wm = warp & 3, wn = warp >> 2;
    int rank = blockIdx.x;

    // static tile list per rank
    int myTiles[2];
    int nT = 0;
    if (rank < 104) {
        myTiles[nT++] = rank;
        if (rank + 104 < 192) myTiles[nT++] = rank + 104;
    } else {
        myTiles[nT++] = rank + 88;    // 192..383
    }

    for (int step = 0; step < NSTEP; step++) {
        int par = step & 1;
        bool ar = (step >= T_OBS);
        const __half* hA = g_hth[par];
        float* Gw = g_G[par];

        // ---- GEMM tiles (dataflow gated per slab) ----
        for (int ti = 0; ti < nT; ti++) {
            int tile = myTiles[ti];
            int tn = tile >> 5;        // 0..11
            int tm = tile & 31;        // slab
            bool needsH = ar || (tn >= 6);
            unsigned tgt = needsH ? 8u * step : (step ? 8u * (step - 1) : 0u);
            if (tgt) spin_ge(&g_gruCnt[tm], tgt);

            const __half* A;
            const __half* W;
            if (tn < 6) {
                A = ar ? hA : (g_H1h + (size_t)step * B * H);
                W = ar ? g_Wih : g_Wch;
            } else {
                A = hA;
                W = g_Whh;
            }
            int wrow = (tn < 6 ? tn : tn - 6) * 128;
            int gcol = tn * 128;
            int mbase = tm * 128;
            const __half* Abase = A + (size_t)mbase * H;
            const __half* Wbase = W + (size_t)wrow * H;

            float acc[2][8][4] = {};

            __syncthreads();   // smem reuse guard across tiles

            // prologue: stages 0..2
#pragma unroll
            for (int s = 0; s < STAGES - 1; s++) {
                int k0 = s * BK;
#pragma unroll
                for (int l = 0; l < 2; l++) {
                    int c = tid + l * 256;
                    int row = c >> 2, seg = c & 3;        // seg = 8-half (16B) chunk
                    cp16(&As[s][row * SROW + seg * 8], Abase + (size_t)row * H + k0 + seg * 8);
                    cp16(&Bs[s][row * SROW + seg * 8], Wbase + (size_t)row * H + k0 + seg * 8);
                }
                asm volatile("cp.async.commit_group;");
            }

#pragma unroll 1
            for (int kc = 0; kc < 8; kc++) {       // 8 chunks of 32
                asm volatile("cp.async.wait_group %0;" :: "n"(STAGES - 2));
                __syncthreads();
                int buf = kc & (STAGES - 1);

                if (kc + STAGES - 1 < 8) {
                    int s = (kc + STAGES - 1) & (STAGES - 1);
                    int k0 = (kc + STAGES - 1) * BK;
#pragma unroll
                    for (int l = 0; l < 2; l++) {
                        int c = tid + l * 256;
                        int row = c >> 2, seg = c & 3;
                        cp16(&As[s][row * SROW + seg * 8], Abase + (size_t)row * H + k0 + seg * 8);
                        cp16(&Bs[s][row * SROW + seg * 8], Wbase + (size_t)row * H + k0 + seg * 8);
                    }
                }
                asm volatile("cp.async.commit_group;");

                const __half* Ab = As[buf];
                const __half* Bb = Bs[buf];
#pragma unroll
                for (int ks = 0; ks < 2; ks++) {   // 2 k16 steps per chunk
                    int kk = ks * 16;
                    unsigned af[2][4], bf[8][2];
#pragma unroll
                    for (int mi = 0; mi < 2; mi++) {
                        int rm = wm * 32 + mi * 16 + q;
                        af[mi][0] = *(const unsigned*)&Ab[rm * SROW + kk + 2 * r];
                        af[mi][1] = *(const unsigned*)&Ab[(rm + 8) * SROW + kk + 2 * r];
                        af[mi][2] = *(const unsigned*)&Ab[rm * SROW + kk + 2 * r + 8];
                        af[mi][3] = *(const unsigned*)&Ab[(rm + 8) * SROW + kk + 2 * r + 8];
                    }
#pragma unroll
                    for (int ni = 0; ni < 8; ni++) {
                        int cn = wn * 64 + ni * 8 + q;
                        bf[ni][0] = *(const unsigned*)&Bb[cn * SROW + kk + 2 * r];
                        bf[ni][1] = *(const unsigned*)&Bb[cn * SROW + kk + 2 * r + 8];
                    }
#pragma unroll
                    for (int mi = 0; mi < 2; mi++)
#pragma unroll
                        for (int ni = 0; ni < 8; ni++)
                            mma_f16(acc[mi][ni], af[mi], bf[ni]);
                }
            }

#pragma unroll
            for (int mi = 0; mi < 2; mi++) {
                int row = mbase + wm * 32 + mi * 16 + q;
#pragma unroll
                for (int ni = 0; ni < 8; ni++) {
                    int cl = wn * 64 + ni * 8 + 2 * r;
                    *(float2*)&Gw[(size_t)row * (2 * G3) + gcol + cl] =
                        make_float2(acc[mi][ni][0], acc[mi][ni][1]);
                    *(float2*)&Gw[(size_t)(row + 8) * (2 * G3) + gcol + cl] =
                        make_float2(acc[mi][ni][2], acc[mi][ni][3]);
                }
            }
            signal(&g_tileCnt[tm]);
        }

        // ---- GRU chunk (16 rows), gated on this slab's 12 tiles ----
        if (rank < GRUCH) {
            int slab = rank >> 3;
            spin_ge(&g_tileCnt[slab], 12u * (step + 1));

            const float* bxi = ar ? bi : g_bc;
            float* hfn = g_hf[par ^ 1];
            __half* htn = g_hth[par ^ 1];
            const float* hfo = g_hf[par];
            float* zs_out = nullptr;
            if (step == T_OBS - 1)      zs_out = zs_base;
            else if (ar)                zs_out = zs_base + (size_t)(step - (T_OBS - 1)) * B * H;

            int row0 = rank * 16;
            for (int i = tid; i < 16 * 64; i += 256) {
                int b = row0 + (i >> 6);
                int m4 = (i & 63) * 4;
                const float* g = Gw + (size_t)b * (2 * G3);
                float4 rx = *(const float4*)(g + m4);
                float4 zx = *(const float4*)(g + H + m4);
                float4 nx = *(const float4*)(g + 2 * H + m4);
                float4 rh = *(const float4*)(g + G3 + m4);
                float4 zh = *(const float4*)(g + G3 + H + m4);
                float4 nh = *(const float4*)(g + G3 + 2 * H + m4);
                float4 br = *(const float4*)(bxi + m4);
                float4 bz = *(const float4*)(bxi + H + m4);
                float4 bn = *(const float4*)(bxi + 2 * H + m4);
                float4 cr = *(const float4*)(bh + m4);
                float4 cz = *(const float4*)(bh + H + m4);
                float4 cn = *(const float4*)(bh + 2 * H + m4);
                float4 hp = *(const float4*)(hfo + (size_t)b * H + m4);
                float4 hn4;
                __half2 hh[2];
#pragma unroll
                for (int c = 0; c < 4; c++) {
                    float gxr = (&rx.x)[c] + (&br.x)[c];
                    float gxz = (&zx.x)[c] + (&bz.x)[c];
                    float gxn = (&nx.x)[c] + (&bn.x)[c];
                    float ghr = (&rh.x)[c] + (&cr.x)[c];
                    float ghz = (&zh.x)[c] + (&cz.x)[c];
                    float ghn = (&nh.x)[c] + (&cn.x)[c];
                    float rr = 1.f / (1.f + expf(-(gxr + ghr)));
                    float ug = 1.f / (1.f + expf(-(gxz + ghz)));
                    float nn = tanhf(gxn + rr * ghn);
                    (&hn4.x)[c] = (1.f - ug) * nn + ug * (&hp.x)[c];
                }
                hh[0] = __floats2half2_rn(hn4.x, hn4.y);
                hh[1] = __floats2half2_rn(hn4.z, hn4.w);
                *(float4*)(hfn + (size_t)b * H + m4) = hn4;
                *(__half2*)(htn + (size_t)b * H + m4)     = hh[0];
                *(__half2*)(htn + (size_t)b * H + m4 + 2) = hh[1];
                if (zs_out) *(float4*)(zs_out + (size_t)b * H + m4) = hn4;
            }
            signal(&g_gruCnt[slab]);
        }
    }
}

// ---------------- head: x_hats = zs @ head_w^T + head_b ----------------
__global__ void head_kernel(const float* __restrict__ zs, const float* __restrict__ head_w,
                            const float* __restrict__ head_b, float* __restrict__ xh) {
    int row = blockIdx.x * 8 + (threadIdx.x >> 5);
    int lane = threadIdx.x & 31;
    const float* z = zs + (size_t)row * H;
    float acc[4] = {0.f, 0.f, 0.f, 0.f};
    for (int c = lane; c < H; c += 32) {
        float zv = z[c];
#pragma unroll
        for (int d = 0; d < 4; d++)
            acc[d] = fmaf(zv, head_w[d * H + c], acc[d]);
    }
#pragma unroll
    for (int d = 0; d < 4; d++)
        for (int off = 16; off; off >>= 1)
            acc[d] += __shfl_xor_sync(0xFFFFFFFFu, acc[d], off);
    if (lane < 4)
        xh[(size_t)row * 4 + lane] = acc[lane] + head_b[lane];
}

// ---------------- launch ----------------
extern "C" void kernel_launch(void* const* d_in, const int* in_sizes, int n_in,
                              void* d_out, int out_size) {
    const float* x_obs   = (const float*)d_in[0];
    const float* t_obs   = (const float*)d_in[1];
    const float* stem_w1 = (const float*)d_in[3];
    const float* stem_b1 = (const float*)d_in[4];
    const float* stem_w2 = (const float*)d_in[5];
    const float* stem_b2 = (const float*)d_in[6];
    const float* gru_wi  = (const float*)d_in[7];
    const float* gru_wh  = (const float*)d_in[8];
    const float* gru_bi  = (const float*)d_in[9];
    const float* gru_bh  = (const float*)d_in[10];
    const float* head_w  = (const float*)d_in[11];
    const float* head_b  = (const float*)d_in[12];

    float* out    = (float*)d_out;
    float* x_hats = out;                                 // [32,4096,4]
    float* zs     = out + (size_t)T_UNOBS * B * D;       // [32,4096,256]

    const int SMEM = STAGES * 128 * SROW * 2 * 2;        // 81920 bytes
    cudaFuncSetAttribute(rnn_persistent,
                         cudaFuncAttributeMaxDynamicSharedMemorySize, SMEM);

    zero_kernel<<<(B * H) / 256, 256>>>();
    round_w_kernel<<<(G3 * H) / 256, 256>>>(gru_wi, gru_wh);
    wc_kernel<<<G3, H>>>(gru_wi, stem_w2, stem_b2, gru_bi);
    stem_kernel<<<T_OBS * B / 16, 256>>>(x_obs, t_obs, stem_w1, stem_b1);

    rnn_persistent<<<NCTA, 256, SMEM>>>(gru_bi, gru_bh, zs);

    head_kernel<<<(T_UNOBS * B) / 8, 256>>>(zs, head_w, head_b, x_hats);
}